// round 1
// baseline (speedup 1.0000x reference)
#include <cuda_runtime.h>
#include <math.h>

#define N_RES   1024
#define DIM     256
#define NB      15
#define E_AB_LO 131072          // gathered edges
#define E_TOT   133120          // + 2*32*32 broadcast edges; = 4160 * 32
#define EPSF    1e-6f
#define TWO_PI  6.283185307179586f

#define TM      32              // edges per block in edge kernel
#define EDGE_BLOCKS (E_TOT / TM)   // 4160

// ---------------- device scratch (no runtime allocation allowed) ----------
__device__ float4 g_rep4[N_RES * (DIM / 4)];  // rep, float4-aligned for vector gathers
__device__ float  g_R[N_RES * 9];             // R[i*3+k] = e_{k}[i]  (columns are e1,e2,e3)
__device__ float  g_t[N_RES * 3];

// ---------------- helpers --------------------------------------------------
__device__ __forceinline__ float gelu_tanh(float x) {
    // jax.nn.gelu default: approximate=True (tanh form)
    float x3 = x * x * x;
    float inner = 0.7978845608028654f * (x + 0.044715f * x3);
    return 0.5f * x * (1.0f + tanhf(inner));
}

__device__ __forceinline__ unsigned long long pack2f(float lo, float hi) {
    unsigned long long r;
    asm("mov.b64 %0, {%1, %2};" : "=l"(r) : "f"(lo), "f"(hi));
    return r;
}
__device__ __forceinline__ void unpack2f(unsigned long long v, float& lo, float& hi) {
    asm("mov.b64 {%0, %1}, %2;" : "=f"(lo), "=f"(hi) : "l"(v));
}
__device__ __forceinline__ void ffma2(unsigned long long& d,
                                      unsigned long long a, unsigned long long b) {
    // packed f32x2 FMA: 2 fp32 FMAs per instruction on sm_103a
    asm("fma.rn.f32x2 %0, %1, %2, %0;" : "+l"(d) : "l"(a), "l"(b));
}

// ---------------- kernel 1: residue MLP (rep) ------------------------------
__global__ void residue_kernel(const float* __restrict__ emb,
                               const float* __restrict__ ts,
                               const float* __restrict__ tf,
                               const float* __restrict__ w1,
                               const float* __restrict__ b1,
                               const float* __restrict__ w2,
                               const float* __restrict__ b2) {
    __shared__ float sx[DIM + 32];
    __shared__ float sh[DIM];
    const int row = blockIdx.x;
    const int t   = threadIdx.x;

    sx[t] = emb[row * DIM + t];
    if (t < 32) {
        float x   = ts[row];
        float f   = tf[t & 15];
        float ang = TWO_PI * x * f;
        sx[DIM + t] = (t < 16) ? sinf(ang) : cosf(ang);
    }
    __syncthreads();

    float acc = b1[t];
    #pragma unroll 4
    for (int k = 0; k < DIM + 32; ++k) acc += sx[k] * w1[k * DIM + t];
    sh[t] = gelu_tanh(acc);
    __syncthreads();

    float acc2 = b2[t];
    #pragma unroll 4
    for (int k = 0; k < DIM; ++k) acc2 += sh[k] * w2[k * DIM + t];

    ((float*)g_rep4)[row * DIM + t] = acc2 + sx[t];   // + residual
}

// ---------------- kernel 2: rigid frames ------------------------------------
__global__ void frames_kernel(const float* __restrict__ coords) {
    int n = blockIdx.x * blockDim.x + threadIdx.x;
    if (n >= N_RES) return;
    const float* c = coords + n * 9;
    float ax = c[0], ay = c[1], az = c[2];
    float bx = c[3], by = c[4], bz = c[5];
    float cx = c[6], cy = c[7], cz = c[8];

    float v1x = cx - bx, v1y = cy - by, v1z = cz - bz;
    float v2x = ax - bx, v2y = ay - by, v2z = az - bz;

    float n1 = sqrtf(v1x * v1x + v1y * v1y + v1z * v1z) + EPSF;
    float e1x = v1x / n1, e1y = v1y / n1, e1z = v1z / n1;

    float dp  = e1x * v2x + e1y * v2y + e1z * v2z;
    float u2x = v2x - e1x * dp, u2y = v2y - e1y * dp, u2z = v2z - e1z * dp;
    float n2  = sqrtf(u2x * u2x + u2y * u2y + u2z * u2z) + EPSF;
    float e2x = u2x / n2, e2y = u2y / n2, e2z = u2z / n2;

    float e3x = e1y * e2z - e1z * e2y;
    float e3y = e1z * e2x - e1x * e2z;
    float e3z = e1x * e2y - e1y * e2x;

    float* R = g_R + n * 9;
    R[0] = e1x; R[1] = e2x; R[2] = e3x;
    R[3] = e1y; R[4] = e2y; R[5] = e3y;
    R[6] = e1z; R[7] = e2z; R[8] = e3z;
    g_t[n * 3 + 0] = bx; g_t[n * 3 + 1] = by; g_t[n * 3 + 2] = bz;
}

// ---------------- kernel 3: fused edge features + edge MLP ------------------
// smem layout (floats):
//   s_in  [TM][704]  edge_in tile
//   s_hid [TM][256]  gelu(edge_in @ w1 + b1)
//   s_gi  [TM][28]   27 geom features (padded)
//   s_disp[TM], s_scale[TM], s_src[TM], s_dst[TM]
#define S_IN_F   (TM * 704)
#define S_HID_F  (TM * 256)
#define S_GI_F   (TM * 28)
#define SMEM_EDGE_BYTES ((S_IN_F + S_HID_F + S_GI_F + TM * 2) * 4 + TM * 2 * 4)

__global__ void __launch_bounds__(256, 1)
edge_kernel(const float* __restrict__ w_geom,
            const float* __restrict__ chain_freq,
            const float* __restrict__ w1e,
            const float* __restrict__ b1e,
            const float* __restrict__ w2e,
            const float* __restrict__ b2e,
            const int* __restrict__ ri,
            const int* __restrict__ cid,
            const int* __restrict__ gA,
            const int* __restrict__ gB,
            const int* __restrict__ pid,
            float* __restrict__ out) {
    extern __shared__ float smem[];
    float* s_in    = smem;                       // TM x 704
    float* s_hid   = s_in + S_IN_F;              // TM x 256
    float* s_gi    = s_hid + S_HID_F;            // TM x 28
    float* s_disp  = s_gi + S_GI_F;
    float* s_scale = s_disp + TM;
    int*   s_src   = (int*)(s_scale + TM);
    int*   s_dst   = s_src + TM;

    const int t = threadIdx.x;

    // ---- Phase A1: per-edge scalars (32 threads) ----
    if (t < TM) {
        int e = blockIdx.x * TM + t;
        int src, dst;
        if (e < E_AB_LO) {
            src = gA[e];
            dst = gB[e];
        } else {
            int r = e - E_AB_LO;
            int bidx = r >> 10;        // / (32*32)
            int w    = r & 1023;
            src = pid[bidx * 32 + (w >> 5)];
            dst = pid[bidx * 32 + (w & 31)];
        }
        s_src[t] = src;
        s_dst[t] = dst;

        float disp = (float)(ri[src] - ri[dst]) * 0.125f;
        float m    = (cid[src] == cid[dst]) ? 1.0f : 0.0f;
        s_disp[t]  = disp;
        s_scale[t] = m / (fabsf(disp) + 1.0f);

        float Rs[9], Rd[9];
        #pragma unroll
        for (int i = 0; i < 9; ++i) { Rs[i] = g_R[src * 9 + i]; Rd[i] = g_R[dst * 9 + i]; }
        float dx = g_t[dst * 3 + 0] - g_t[src * 3 + 0];
        float dy = g_t[dst * 3 + 1] - g_t[src * 3 + 1];
        float dz = g_t[dst * 3 + 2] - g_t[src * 3 + 2];
        float dist = sqrtf(dx * dx + dy * dy + dz * dz + EPSF);

        float* gi = s_gi + t * 28;
        // rbf: centers linspace(0,20,15), sig = 20/15
        const float inv_sig = 15.0f / 20.0f;           // 0.75
        #pragma unroll
        for (int i = 0; i < NB; ++i) {
            float cc = (20.0f / 14.0f) * (float)i;
            float z  = (dist - cc) * inv_sig;
            gi[i] = expf(-0.5f * z * z);
        }
        // relrot[a*3+b] = sum_i Rs[i][a] * Rd[i][b]
        #pragma unroll
        for (int a = 0; a < 3; ++a)
            #pragma unroll
            for (int b = 0; b < 3; ++b)
                gi[15 + a * 3 + b] = Rs[0 + a] * Rd[0 + b] + Rs[3 + a] * Rd[3 + b] + Rs[6 + a] * Rd[6 + b];
        // local_k = (R_src^T d)_k / (dist + 1)
        float inv = 1.0f / (dist + 1.0f);
        #pragma unroll
        for (int k = 0; k < 3; ++k)
            gi[24 + k] = (Rs[k] * dx + Rs[3 + k] * dy + Rs[6 + k] * dz) * inv;
    }
    __syncthreads();

    const int eg = t >> 3;       // edge 0..31
    const int p  = t & 7;        // part 0..7

    // ---- Phase A2: geom = gi(27) @ w_geom(27x128) -> s_in[:,0:128] ----
    {
        float acc[16];
        #pragma unroll
        for (int q = 0; q < 16; ++q) acc[q] = 0.0f;
        const float* gi = s_gi + eg * 28;
        #pragma unroll
        for (int k = 0; k < 27; ++k) {
            float g = gi[k];
            const float* wg = w_geom + k * 128 + p * 16;
            #pragma unroll
            for (int q = 0; q < 16; ++q) acc[q] += g * wg[q];
        }
        float* drow = s_in + eg * 704;
        #pragma unroll
        for (int q = 0; q < 16; ++q) drow[p * 16 + q] = acc[q];
    }

    // ---- Phase A3: rope(64) -> s_in[:,128:192] ----
    {
        float disp = s_disp[eg];
        float sc   = s_scale[eg];
        float* drow = s_in + eg * 704 + 128;
        #pragma unroll
        for (int u = 0; u < 8; ++u) {
            int idx = p * 8 + u;
            float f   = chain_freq[idx & 31];
            float ang = TWO_PI * disp * f;
            drow[idx] = ((idx < 32) ? sinf(ang) : cosf(ang)) * sc;
        }
    }

    // ---- Phase A4: gather rep[src], rep[dst] -> s_in[:,192:704] ----
    {
        #pragma unroll
        for (int it = 0; it < 16; ++it) {
            int v    = t + it * 256;       // 0..4095 float4 chunks
            int e2   = v >> 7;
            int r    = v & 127;
            int half = r >> 6;
            int q    = r & 63;
            int idx  = half ? s_dst[e2] : s_src[e2];
            float4 val = g_rep4[idx * 64 + q];
            *(float4*)(s_in + e2 * 704 + 192 + half * 256 + q * 4) = val;
        }
    }
    __syncthreads();

    // ---- Phase B: GEMM1  hidden[32x256] = gelu(s_in @ w1e + b1e) ----
    const int lane = t & 31;
    const int mg   = t >> 5;     // 0..7 -> rows mg*4 .. mg*4+3
    {
        unsigned long long acc[4][4];
        #pragma unroll
        for (int m = 0; m < 4; ++m)
            #pragma unroll
            for (int q = 0; q < 4; ++q) acc[m][q] = 0ull;

        const float* a0 = s_in + (mg * 4 + 0) * 704;
        const float* a1 = s_in + (mg * 4 + 1) * 704;
        const float* a2 = s_in + (mg * 4 + 2) * 704;
        const float* a3 = s_in + (mg * 4 + 3) * 704;
        const char*  wp = (const char*)(w1e + lane * 8);

        #pragma unroll 4
        for (int k = 0; k < 704; ++k) {
            float av0 = a0[k], av1 = a1[k], av2 = a2[k], av3 = a3[k];
            ulonglong2 b01 = *(const ulonglong2*)(wp);
            ulonglong2 b23 = *(const ulonglong2*)(wp + 16);
            wp += 1024;
            unsigned long long A0 = pack2f(av0, av0);
            unsigned long long A1 = pack2f(av1, av1);
            unsigned long long A2 = pack2f(av2, av2);
            unsigned long long A3 = pack2f(av3, av3);
            ffma2(acc[0][0], A0, b01.x); ffma2(acc[0][1], A0, b01.y);
            ffma2(acc[0][2], A0, b23.x); ffma2(acc[0][3], A0, b23.y);
            ffma2(acc[1][0], A1, b01.x); ffma2(acc[1][1], A1, b01.y);
            ffma2(acc[1][2], A1, b23.x); ffma2(acc[1][3], A1, b23.y);
            ffma2(acc[2][0], A2, b01.x); ffma2(acc[2][1], A2, b01.y);
            ffma2(acc[2][2], A2, b23.x); ffma2(acc[2][3], A2, b23.y);
            ffma2(acc[3][0], A3, b01.x); ffma2(acc[3][1], A3, b01.y);
            ffma2(acc[3][2], A3, b23.x); ffma2(acc[3][3], A3, b23.y);
        }

        #pragma unroll
        for (int m = 0; m < 4; ++m) {
            int erow = mg * 4 + m;
            #pragma unroll
            for (int q = 0; q < 4; ++q) {
                float lo, hi;
                unpack2f(acc[m][q], lo, hi);
                int j = lane * 8 + q * 2;
                s_hid[erow * 256 + j]     = gelu_tanh(lo + b1e[j]);
                s_hid[erow * 256 + j + 1] = gelu_tanh(hi + b1e[j + 1]);
            }
        }
    }
    __syncthreads();

    // ---- Phase C: GEMM2  out[32x128] = s_hid @ w2e + b2e ----
    {
        unsigned long long acc[4][2];
        #pragma unroll
        for (int m = 0; m < 4; ++m) { acc[m][0] = 0ull; acc[m][1] = 0ull; }

        const float* h0 = s_hid + (mg * 4 + 0) * 256;
        const float* h1 = s_hid + (mg * 4 + 1) * 256;
        const float* h2 = s_hid + (mg * 4 + 2) * 256;
        const float* h3 = s_hid + (mg * 4 + 3) * 256;
        const char*  wp = (const char*)(w2e + lane * 4);

        #pragma unroll 4
        for (int k = 0; k < 256; ++k) {
            float hv0 = h0[k], hv1 = h1[k], hv2 = h2[k], hv3 = h3[k];
            ulonglong2 b = *(const ulonglong2*)(wp);
            wp += 512;
            unsigned long long H0 = pack2f(hv0, hv0);
            unsigned long long H1 = pack2f(hv1, hv1);
            unsigned long long H2 = pack2f(hv2, hv2);
            unsigned long long H3 = pack2f(hv3, hv3);
            ffma2(acc[0][0], H0, b.x); ffma2(acc[0][1], H0, b.y);
            ffma2(acc[1][0], H1, b.x); ffma2(acc[1][1], H1, b.y);
            ffma2(acc[2][0], H2, b.x); ffma2(acc[2][1], H2, b.y);
            ffma2(acc[3][0], H3, b.x); ffma2(acc[3][1], H3, b.y);
        }

        float bb0 = b2e[lane * 4 + 0];
        float bb1 = b2e[lane * 4 + 1];
        float bb2 = b2e[lane * 4 + 2];
        float bb3 = b2e[lane * 4 + 3];

        #pragma unroll
        for (int m = 0; m < 4; ++m) {
            float o0, o1, o2, o3;
            unpack2f(acc[m][0], o0, o1);
            unpack2f(acc[m][1], o2, o3);
            int eglob = blockIdx.x * TM + mg * 4 + m;
            float4 v = make_float4(o0 + bb0, o1 + bb1, o2 + bb2, o3 + bb3);
            *(float4*)(out + eglob * 128 + lane * 4) = v;
        }
    }
}

// ---------------- launch ----------------------------------------------------
extern "C" void kernel_launch(void* const* d_in, const int* in_sizes, int n_in,
                              void* d_out, int out_size) {
    const float* emb        = (const float*)d_in[0];   // res_embedding_in  [1024,256]
    const float* ts         = (const float*)d_in[1];   // timestep          [1024,1]
    const float* coords     = (const float*)d_in[2];   // coords            [1024,3,3]
    const float* time_freq  = (const float*)d_in[3];   // [16]
    const float* chain_freq = (const float*)d_in[4];   // [32]
    const float* w1_res     = (const float*)d_in[5];   // [288,256]
    const float* b1_res     = (const float*)d_in[6];
    const float* w2_res     = (const float*)d_in[7];   // [256,256]
    const float* b2_res     = (const float*)d_in[8];
    const float* w_geom     = (const float*)d_in[9];   // [27,128]
    const float* w1_edge    = (const float*)d_in[10];  // [704,256]
    const float* b1_edge    = (const float*)d_in[11];
    const float* w2_edge    = (const float*)d_in[12];  // [256,128]
    const float* b2_edge    = (const float*)d_in[13];
    const int*   ri         = (const int*)d_in[14];    // residue_index
    const int*   cid        = (const int*)d_in[15];    // res_chain_id
    const int*   gA         = (const int*)d_in[16];    // gather_idx_ab_a
    const int*   gB         = (const int*)d_in[17];    // gather_idx_ab_b
    const int*   pid        = (const int*)d_in[18];    // gather_idx_pid_a
    float* out = (float*)d_out;

    cudaFuncSetAttribute(edge_kernel, cudaFuncAttributeMaxDynamicSharedMemorySize,
                         SMEM_EDGE_BYTES);

    residue_kernel<<<N_RES, 256>>>(emb, ts, time_freq, w1_res, b1_res, w2_res, b2_res);
    frames_kernel<<<(N_RES + 255) / 256, 256>>>(coords);
    edge_kernel<<<EDGE_BLOCKS, 256, SMEM_EDGE_BYTES>>>(
        w_geom, chain_freq, w1_edge, b1_edge, w2_edge, b2_edge,
        ri, cid, gA, gB, pid, out);
}